// round 8
// baseline (speedup 1.0000x reference)
#include <cuda_runtime.h>
#include <cstdint>

// LoRA forward: out = (x @ B) @ A * 2
//   x: [8192, 4096] fp32, B: [4096, 16], A: [16, 4096], out: [8192, 4096]
//  lora_xb : thread <-> (row, split). x via direct LDG.128 (no staging),
//            B broadcast from once-staged smem. SPLIT=16 -> partial xb.
//  lora_out: sums 16 partials, A (16r x 8 cols) in 64 regs, xb broadcast
//            from smem, packed f32x2 throughout.

#define ROWS_TOTAL 8192
#define IN_DIM     4096
#define OUT_DIM    4096
#define R_DIM      16

#define XB_SPLIT   16
#define XB_ISPAN   (IN_DIM / XB_SPLIT)     // 256 i per thread

typedef unsigned long long u64;

// partial xb: [split][row][8] u64, each u64 = (xb_{2j}, xb_{2j+1}), scaled by 2
__device__ u64 g_xbp[XB_SPLIT][ROWS_TOTAL][R_DIM / 2];

// ---------- packed f32x2 helpers ----------
__device__ __forceinline__ u64 pack2(float lo, float hi) {
    u64 r; asm("mov.b64 %0, {%1, %2};" : "=l"(r) : "f"(lo), "f"(hi)); return r;
}
__device__ __forceinline__ void ffma2(u64& d, u64 a, u64 b) {
    asm("fma.rn.f32x2 %0, %1, %2, %0;" : "+l"(d) : "l"(a), "l"(b));
}
__device__ __forceinline__ void addf2(u64& d, u64 a, u64 b) {
    asm("add.rn.f32x2 %0, %1, %2;" : "=l"(d) : "l"(a), "l"(b));
}
__device__ __forceinline__ void mulf2(u64& d, u64 a, u64 b) {
    asm("mul.rn.f32x2 %0, %1, %2;" : "=l"(d) : "l"(a), "l"(b));
}
__device__ __forceinline__ void unpack2(u64 v, float& lo, float& hi) {
    asm("mov.b64 {%0, %1}, %2;" : "=f"(lo), "=f"(hi) : "l"(v));
}

// ---------- kernel A: partial xb ----------
// grid 512 x 256 threads. Block b: split = b>>5, rows [ (b&31)*256, +256 ).
// Thread owns one row's 256-i span: 8 u64 accumulators, x streamed via
// LDG.128 (4 float4 in flight), B[i][0..15] = 2 broadcast LDS.128 per i.
__global__ void __launch_bounds__(256) lora_xb(const float* __restrict__ x,
                                               const float* __restrict__ B) {
    __shared__ float bs[XB_ISPAN * R_DIM];   // 16 KB: block's B span, native

    const int tid   = threadIdx.x;
    const int split = blockIdx.x >> 5;
    const int row   = (blockIdx.x & 31) * 256 + tid;
    const int i0    = split * XB_ISPAN;

    // stage B span once: 256 rows x 4 float4 = 1024 float4 -> 4 per thread
    {
        const float4* Bg  = reinterpret_cast<const float4*>(B);
        float4*       bs4 = reinterpret_cast<float4*>(bs);
#pragma unroll
        for (int k = 0; k < 4; k++)
            bs4[tid + k * 256] = Bg[(size_t)i0 * 4 + tid + k * 256];
    }
    __syncthreads();

    const float4*     xg  = reinterpret_cast<const float4*>(x) + (size_t)row * (IN_DIM / 4) + (i0 >> 2);
    const ulonglong2* bs2 = reinterpret_cast<const ulonglong2*>(bs);

    u64 acc[8];
#pragma unroll
    for (int j = 0; j < 8; j++) acc[j] = 0ull;

#pragma unroll 1
    for (int ic = 0; ic < XB_ISPAN / 4; ic += 4) {   // 16 outer iters, 16 i each
        float4 xv[4];
#pragma unroll
        for (int k = 0; k < 4; k++) xv[k] = xg[ic + k];   // 4 LDG.128 in flight

#pragma unroll
        for (int k = 0; k < 4; k++) {
            float xe[4] = {xv[k].x, xv[k].y, xv[k].z, xv[k].w};
#pragma unroll
            for (int e = 0; e < 4; e++) {
                const int il = (ic + k) * 4 + e;          // local i, warp-uniform
                ulonglong2 b01 = bs2[il * 4 + 0];         // bcast LDS.128: r0..3
                ulonglong2 b23 = bs2[il * 4 + 1];         // r4..7
                ulonglong2 b45 = bs2[il * 4 + 2];         // r8..11
                ulonglong2 b67 = bs2[il * 4 + 3];         // r12..15
                u64 xx = pack2(xe[e], xe[e]);
                ffma2(acc[0], xx, b01.x);
                ffma2(acc[1], xx, b01.y);
                ffma2(acc[2], xx, b23.x);
                ffma2(acc[3], xx, b23.y);
                ffma2(acc[4], xx, b45.x);
                ffma2(acc[5], xx, b45.y);
                ffma2(acc[6], xx, b67.x);
                ffma2(acc[7], xx, b67.y);
            }
        }
    }

    // scale by 2 (LoRA alpha/rank) and write this row's partial: 64 B contig
    u64 two = pack2(2.0f, 2.0f);
    ulonglong2* gp = reinterpret_cast<ulonglong2*>(&g_xbp[split][row][0]);
#pragma unroll
    for (int j = 0; j < 4; j++) {
        u64 a, b;
        mulf2(a, acc[2 * j + 0], two);
        mulf2(b, acc[2 * j + 1], two);
        ulonglong2 v; v.x = a; v.y = b;
        gp[j] = v;                             // STG.128, coalesced across lanes
    }
}

// ---------- kernel B: out = xb @ A ----------
// 128 threads; block = 64 rows x 1024 cols (8 cols per thread). A slice
// (16 r x 2 ulonglong2) in 64 regs; xb broadcast from smem. Grid 512.
#define O_ROWS 64

__global__ void __launch_bounds__(128, 4) lora_out(const float* __restrict__ A,
                                                   float* __restrict__ out) {
    __shared__ u64 xbs[O_ROWS * R_DIM];   // 8 KB, entries packed (v,v)

    const int tid    = threadIdx.x;
    const int rowblk = blockIdx.x >> 2;
    const int colblk = blockIdx.x & 3;
    const int row0   = rowblk * O_ROWS;

    // fill xbs: 64 rows * 8 u64-slots = 512 -> 4 per thread; sum 16 splits
    {
        const u64* gp = &g_xbp[0][row0][0];
        const size_t sstr = (size_t)ROWS_TOTAL * (R_DIM / 2);   // split stride
#pragma unroll
        for (int k = 0; k < 4; k++) {
            int j = tid + k * 128;            // j -> (row = j>>3, slot = j&7)
            u64 s = gp[j];
#pragma unroll
            for (int sp = 1; sp < XB_SPLIT; sp++)
                addf2(s, s, gp[sp * sstr + j]);
            float f0, f1;
            unpack2(s, f0, f1);
            int rw = j >> 3, slot = j & 7;
            xbs[rw * R_DIM + slot * 2 + 0] = pack2(f0, f0);
            xbs[rw * R_DIM + slot * 2 + 1] = pack2(f1, f1);
        }
    }
    __syncthreads();

    // A slice into registers: 16 r x 2 ulonglong2 (8 cols), coalesced
    const ulonglong2* Av = reinterpret_cast<const ulonglong2*>(A);  // [16][1024]
    const int cu = colblk * 256 + tid * 2;   // ulonglong2 index within a row
    ulonglong2 Ar[R_DIM][2];
#pragma unroll
    for (int rr = 0; rr < R_DIM; rr++) {
        Ar[rr][0] = Av[(size_t)rr * (OUT_DIM / 4) + cu];
        Ar[rr][1] = Av[(size_t)rr * (OUT_DIM / 4) + cu + 1];
    }

    ulonglong2* outv = reinterpret_cast<ulonglong2*>(out);
    const ulonglong2* xu = reinterpret_cast<const ulonglong2*>(xbs);

#pragma unroll 2
    for (int rw = 0; rw < O_ROWS; rw++) {
        u64 accE[4], accO[4];
#pragma unroll
        for (int c = 0; c < 4; c++) { accE[c] = 0ull; accO[c] = 0ull; }

#pragma unroll
        for (int q = 0; q < 8; q++) {
            ulonglong2 xq = xu[rw * 8 + q];   // bcast: (xb_2q,xb_2q),(xb_2q+1,..)
            ulonglong2 e0 = Ar[2 * q][0],     e1 = Ar[2 * q][1];
            ulonglong2 o0 = Ar[2 * q + 1][0], o1 = Ar[2 * q + 1][1];
            ffma2(accE[0], xq.x, e0.x);
            ffma2(accE[1], xq.x, e0.y);
            ffma2(accE[2], xq.x, e1.x);
            ffma2(accE[3], xq.x, e1.y);
            ffma2(accO[0], xq.y, o0.x);
            ffma2(accO[1], xq.y, o0.y);
            ffma2(accO[2], xq.y, o1.x);
            ffma2(accO[3], xq.y, o1.y);
        }

        u64 o0, o1, o2, o3;
        addf2(o0, accE[0], accO[0]);
        addf2(o1, accE[1], accO[1]);
        addf2(o2, accE[2], accO[2]);
        addf2(o3, accE[3], accO[3]);
        ulonglong2 v0; v0.x = o0; v0.y = o1;
        ulonglong2 v1; v1.x = o2; v1.y = o3;
        const size_t ro = (size_t)(row0 + rw) * (OUT_DIM / 4);
        outv[ro + cu]     = v0;               // STG.128 x2, 32B/thread contig
        outv[ro + cu + 1] = v1;
    }
}

// ---------- launch ----------
extern "C" void kernel_launch(void* const* d_in, const int* in_sizes, int n_in,
                              void* d_out, int out_size) {
    const float* x  = (const float*)d_in[0];   // [4, 2048, 4096]
    const float* lA = (const float*)d_in[1];   // [16, 4096]
    const float* lB = (const float*)d_in[2];   // [4096, 16]
    float* out = (float*)d_out;

    lora_xb<<<(ROWS_TOTAL / 256) * XB_SPLIT, 256>>>(x, lB);
    lora_out<<<(ROWS_TOTAL / O_ROWS) * (OUT_DIM / 1024), 128>>>(lA, out);
}

// round 9
// speedup vs baseline: 1.3602x; 1.3602x over previous
#include <cuda_runtime.h>
#include <cstdint>

// LoRA forward: out = (x @ B) @ A * 2
//   x: [8192, 4096] fp32, B: [4096, 16], A: [16, 4096], out: [8192, 4096]
//  lora_xb : warp owns 4 rows x full i. B in registers (coalesced 1KB warp
//            loads, L1-resident), x via coalesced LDG.32, shfl-butterfly
//            reduction. No smem, no partials.
//  lora_out: A (16r x 4 cols) in regs, xb broadcast from smem, f32x2 (R4 cfg).

#define ROWS_TOTAL 8192
#define IN_DIM     4096
#define OUT_DIM    4096
#define R_DIM      16

typedef unsigned long long u64;

// xb = 2 * (x @ B): [row][8] u64, slot j = (xb_{2j}, xb_{2j+1})
__device__ u64 g_xb[ROWS_TOTAL * (R_DIM / 2)];

// ---------- packed f32x2 helpers ----------
__device__ __forceinline__ u64 pack2(float lo, float hi) {
    u64 r; asm("mov.b64 %0, {%1, %2};" : "=l"(r) : "f"(lo), "f"(hi)); return r;
}
__device__ __forceinline__ void unpack2(u64 v, float& lo, float& hi) {
    asm("mov.b64 {%0, %1}, %2;" : "=f"(lo), "=f"(hi) : "l"(v));
}
__device__ __forceinline__ void ffma2(u64& d, u64 a, u64 b) {
    asm("fma.rn.f32x2 %0, %1, %2, %0;" : "+l"(d) : "l"(a), "l"(b));
}
__device__ __forceinline__ void addf2(u64& d, u64 a, u64 b) {
    asm("add.rn.f32x2 %0, %1, %2;" : "=l"(d) : "l"(a), "l"(b));
}
__device__ __forceinline__ void mulf2(u64& d, u64 a, u64 b) {
    asm("mul.rn.f32x2 %0, %1, %2;" : "=l"(d) : "l"(a), "l"(b));
}

// ---------- kernel A: xb = 2 * x @ B ----------
// 256 threads = 8 warps; 256 blocks. Warp gw handles rows [gw*4, gw*4+4).
// lane: il = lane&15 (i offset), rh = lane>>4 (r-half). 64 chunks of 64 i.
// Per chunk: B regs b[k][4] via 8 coalesced LDG.128 (1KB fully used per
// instr-pair); x via LDG.32 (64B contiguous per instr, rh-dup dedup'd);
// 64 ffma2. Final: xor-butterfly over 16-lane group, lanes 0/16 store.
__global__ void __launch_bounds__(256, 2) lora_xb(const float* __restrict__ x,
                                                  const float* __restrict__ B) {
    const int tid  = threadIdx.x;
    const int wid  = tid >> 5;
    const int lane = tid & 31;
    const int il   = lane & 15;
    const int rh   = lane >> 4;
    const int gw   = blockIdx.x * 8 + wid;
    const int r0   = gw * 4;                 // first of 4 rows

    const ulonglong2* Bv = reinterpret_cast<const ulonglong2*>(B);
    const float* xp = x + (size_t)r0 * IN_DIM + il;   // + k*16 + ch*64 later

    u64 acc[4][4];
#pragma unroll
    for (int rw = 0; rw < 4; rw++)
#pragma unroll
        for (int j = 0; j < 4; j++) acc[rw][j] = 0ull;

#pragma unroll 1
    for (int ch = 0; ch < IN_DIM / 64; ch++) {
        // B for this chunk: lane's i = ch*64 + k*16 + il, rh-half (8 floats)
        u64 b[4][4];
#pragma unroll
        for (int k = 0; k < 4; k++) {
            const int i = ch * 64 + k * 16 + il;
            ulonglong2 p0 = Bv[(size_t)i * 4 + rh * 2];       // r-half lo 16B
            ulonglong2 p1 = Bv[(size_t)i * 4 + rh * 2 + 1];   // r-half hi 16B
            b[k][0] = p0.x; b[k][1] = p0.y;
            b[k][2] = p1.x; b[k][3] = p1.y;
        }

        // x + FMA: 4 rows x 4 k
#pragma unroll
        for (int rw = 0; rw < 4; rw++) {
            const float* xr = xp + (size_t)rw * IN_DIM + ch * 64;
            float xv[4];
#pragma unroll
            for (int k = 0; k < 4; k++) xv[k] = xr[k * 16];   // LDG.32 coalesced
#pragma unroll
            for (int k = 0; k < 4; k++) {
                u64 xx = pack2(xv[k], xv[k]);
                ffma2(acc[rw][0], xx, b[k][0]);
                ffma2(acc[rw][1], xx, b[k][1]);
                ffma2(acc[rw][2], xx, b[k][2]);
                ffma2(acc[rw][3], xx, b[k][3]);
            }
        }
    }

    // reduce across the 16 il-lanes (xor 1,2,4,8 stays within rh group)
#pragma unroll
    for (int m = 1; m <= 8; m <<= 1)
#pragma unroll
        for (int rw = 0; rw < 4; rw++)
#pragma unroll
            for (int j = 0; j < 4; j++) {
                u64 o = __shfl_xor_sync(0xffffffffu, acc[rw][j], m);
                addf2(acc[rw][j], acc[rw][j], o);
            }

    if (il == 0) {
        u64 two = pack2(2.0f, 2.0f);         // LoRA scale folded here
#pragma unroll
        for (int rw = 0; rw < 4; rw++) {
            u64 s0, s1, s2, s3;
            mulf2(s0, acc[rw][0], two);
            mulf2(s1, acc[rw][1], two);
            mulf2(s2, acc[rw][2], two);
            mulf2(s3, acc[rw][3], two);
            ulonglong2* gp = reinterpret_cast<ulonglong2*>(
                &g_xb[(size_t)(r0 + rw) * 8 + rh * 4]);
            ulonglong2 v0; v0.x = s0; v0.y = s1;
            ulonglong2 v1; v1.x = s2; v1.y = s3;
            gp[0] = v0;
            gp[1] = v1;
        }
    }
}

// ---------- kernel B: out = xb @ A (proven R4 config) ----------
// 128 threads; block covers 64 rows x 512 cols. A slice (16 r x 1 ulonglong2)
// in 32 regs; xb broadcast from smem via LDS.128. Grid 1024.
#define O_ROWS 64

__global__ void __launch_bounds__(128, 4) lora_out(const float* __restrict__ A,
                                                   float* __restrict__ out) {
    __shared__ u64 xbs[O_ROWS * R_DIM];   // 8 KB, entries packed (v,v)

    const int tid    = threadIdx.x;
    const int rowblk = blockIdx.x >> 3;
    const int colblk = blockIdx.x & 7;
    const int row0   = rowblk * O_ROWS;

    // fill xbs: 64 rows * 8 u64-slots = 512 -> 4 per thread
    {
        const u64* gp = &g_xb[(size_t)row0 * 8];
#pragma unroll
        for (int k = 0; k < 4; k++) {
            int j = tid + k * 128;            // j -> (row = j>>3, slot = j&7)
            u64 s = gp[j];
            float f0, f1;
            unpack2(s, f0, f1);
            int rw = j >> 3, slot = j & 7;
            xbs[rw * R_DIM + slot * 2 + 0] = pack2(f0, f0);
            xbs[rw * R_DIM + slot * 2 + 1] = pack2(f1, f1);
        }
    }
    __syncthreads();

    // A slice into registers: 16 r x 1 ulonglong2 (4 cols), coalesced
    const ulonglong2* Av = reinterpret_cast<const ulonglong2*>(A);  // [16][1024]
    const int cu = colblk * 128 + tid;    // ulonglong2 index within a row
    ulonglong2 Ar[R_DIM];
#pragma unroll
    for (int rr = 0; rr < R_DIM; rr++)
        Ar[rr] = Av[(size_t)rr * (OUT_DIM / 4) + cu];

    ulonglong2* outv = reinterpret_cast<ulonglong2*>(out);
    const ulonglong2* xu = reinterpret_cast<const ulonglong2*>(xbs);

#pragma unroll 2
    for (int rw = 0; rw < O_ROWS; rw++) {
        u64 a0e = 0ull, a0o = 0ull, a1e = 0ull, a1o = 0ull;
#pragma unroll
        for (int q = 0; q < 8; q++) {
            ulonglong2 xq = xu[rw * 8 + q];   // bcast (xb_2q,xb_2q),(xb_2q+1,..)
            ffma2(a0e, xq.x, Ar[2 * q].x);
            ffma2(a1e, xq.x, Ar[2 * q].y);
            ffma2(a0o, xq.y, Ar[2 * q + 1].x);
            ffma2(a1o, xq.y, Ar[2 * q + 1].y);
        }
        u64 o0, o1;
        addf2(o0, a0e, a0o);
        addf2(o1, a1e, a1o);
        ulonglong2 v; v.x = o0; v.y = o1;
        outv[(size_t)(row0 + rw) * (OUT_DIM / 4) + cu] = v;   // STG.128 coalesced
    }
}

// ---------- launch ----------
extern "C" void kernel_launch(void* const* d_in, const int* in_sizes, int n_in,
                              void* d_out, int out_size) {
    const float* x  = (const float*)d_in[0];   // [4, 2048, 4096]
    const float* lA = (const float*)d_in[1];   // [16, 4096]
    const float* lB = (const float*)d_in[2];   // [4096, 16]
    float* out = (float*)d_out;

    lora_xb<<<ROWS_TOTAL / 32, 256>>>(x, lB);                    // 256 blocks
    lora_out<<<(ROWS_TOTAL / O_ROWS) * (OUT_DIM / 512), 128>>>(lA, out);
}

// round 10
// speedup vs baseline: 1.6148x; 1.1871x over previous
#include <cuda_runtime.h>
#include <cstdint>

// LoRA forward: out = (x @ B) @ A * 2
//   x: [8192, 4096] fp32, B: [4096, 16], A: [16, 4096], out: [8192, 4096]
//  lora_xb : R7 design (best measured ~35us): 64 rows/block, 2 rows/lane,
//            i-split x2, 4-stage cp.async pipeline (AT=32), 1 barrier/tile.
//  lora_out: R4 design (best measured ~29us): A slice in regs, xb broadcast
//            from smem, f32x2, 512-col blocks.
// Each kernel launched as 2 row-halves (period-4 pattern -> ncu lands on xb).

#define ROWS_TOTAL 8192
#define IN_DIM     4096
#define OUT_DIM    4096
#define R_DIM      16

#define XB_SPLIT   2
#define XB_ISPAN   (IN_DIM / XB_SPLIT)     // 2048 i per block
#define XB_AT      32                       // i per tile
#define XB_NT      (XB_ISPAN / XB_AT)       // 64 tiles
#define XB_ROWS    64                       // rows per block (2 per lane)
#define XB_STAGES  4

typedef unsigned long long u64;

// partial xb: [split][row][8] u64, each u64 = (xb_{2j}, xb_{2j+1}), scaled by 2
__device__ u64 g_xbp[XB_SPLIT][ROWS_TOTAL][R_DIM / 2];

// ---------- packed f32x2 helpers ----------
__device__ __forceinline__ u64 pack2(float lo, float hi) {
    u64 r; asm("mov.b64 %0, {%1, %2};" : "=l"(r) : "f"(lo), "f"(hi)); return r;
}
__device__ __forceinline__ void unpack2(u64 v, float& lo, float& hi) {
    asm("mov.b64 {%0, %1}, %2;" : "=f"(lo), "=f"(hi) : "l"(v));
}
__device__ __forceinline__ void ffma2(u64& d, u64 a, u64 b) {
    asm("fma.rn.f32x2 %0, %1, %2, %0;" : "+l"(d) : "l"(a), "l"(b));
}
__device__ __forceinline__ void addf2(u64& d, u64 a, u64 b) {
    asm("add.rn.f32x2 %0, %1, %2;" : "=l"(d) : "l"(a), "l"(b));
}
__device__ __forceinline__ void mulf2(u64& d, u64 a, u64 b) {
    asm("mul.rn.f32x2 %0, %1, %2;" : "=l"(d) : "l"(a), "l"(b));
}

// ---------- cp.async helpers ----------
__device__ __forceinline__ uint32_t s2u(const void* p) {
    return (uint32_t)__cvta_generic_to_shared(p);
}
__device__ __forceinline__ void cp16(uint32_t dst, const void* src) {
    asm volatile("cp.async.cg.shared.global [%0], [%1], 16;"
                 :: "r"(dst), "l"(src) : "memory");
}
#define CP_COMMIT()  asm volatile("cp.async.commit_group;" ::: "memory")
#define CP_WAIT(N)   asm volatile("cp.async.wait_group %0;" :: "n"(N) : "memory")

// ---------- kernel A: partial xb (R7 design + row_base) ----------
// 256 threads = 8 warps; lane covers rows {lane, lane+32}. Warp w covers
// i-subrange [w*4, w*4+4) of each 32-i tile. B consumed in NATIVE layout via
// broadcast LDS.128; x staged XOR-swizzled. 4-stage cp.async pipeline
// (prefetch depth 3), one barrier per tile.
__global__ void __launch_bounds__(256, 3) lora_xb(const float* __restrict__ x,
                                                  const float* __restrict__ B,
                                                  int row_base) {
    __shared__ float xs[XB_STAGES][XB_ROWS][XB_AT];   // 4 x 8 KB
    __shared__ float bs[XB_STAGES][XB_AT][R_DIM];     // 4 x 2 KB

    const int tid   = threadIdx.x;
    const int wid   = tid >> 5;
    const int lane  = tid & 31;
    const int row0  = row_base + (blockIdx.x >> 1) * XB_ROWS;
    const int i0    = (blockIdx.x & 1) * XB_ISPAN;
    const int split = blockIdx.x & 1;

    const float4* xg = reinterpret_cast<const float4*>(x);
    const float4* Bg = reinterpret_cast<const float4*>(B);   // B row i = 4 float4

    auto stage = [&](int it, int buf) {
        float4* xs4 = reinterpret_cast<float4*>(&xs[buf][0][0]);   // [64][8]
        float4* bs4 = reinterpret_cast<float4*>(&bs[buf][0][0]);   // [128]
        // x: 64 rows x 8 float4 = 512 -> 2 per thread, XOR-swizzled dst
#pragma unroll
        for (int k = 0; k < 2; k++) {
            int f  = tid + k * 256;
            int rw = f >> 3;          // 0..63
            int c4 = f & 7;           // 0..7
            cp16(s2u(&xs4[rw * 8 + (c4 ^ (rw & 7))]),
                 &xg[(size_t)(row0 + rw) * (IN_DIM / 4) + (i0 >> 2) + it * (XB_AT / 4) + c4]);
        }
        // B tile: 32 rows x 4 float4 = 128 contiguous -> threads 0..127
        if (tid < 128)
            cp16(s2u(&bs4[tid]), &Bg[(size_t)(i0 + it * XB_AT) * 4 + tid]);
        CP_COMMIT();
    };

    stage(0, 0);
    stage(1, 1);
    stage(2, 2);

    u64 acc[2][8];
#pragma unroll
    for (int s = 0; s < 2; s++)
#pragma unroll
        for (int j = 0; j < 8; j++) acc[s][j] = 0ull;

    for (int it = 0; it < XB_NT; it++) {
        const int buf = it % XB_STAGES;
        // complete tile `it`; keep the prefetched ones pending
        if      (it <= XB_NT - 3) { CP_WAIT(2); }
        else if (it == XB_NT - 2) { CP_WAIT(1); }
        else                      { CP_WAIT(0); }
        __syncthreads();   // tile `it` visible; compute of it-1 done everywhere,
                           // so buf (it+3)%4 (= buf of it-1) is free to restage
        if (it + 3 < XB_NT) stage(it + 3, (it + 3) % XB_STAGES);

        const float4*     xs4 = reinterpret_cast<const float4*>(&xs[buf][0][0]);
        const ulonglong2* bs2 = reinterpret_cast<const ulonglong2*>(&bs[buf][0][0]);

        // warp's i-slice: [wid*4, wid*4+4) = one float4 per row
        float4 xq0 = xs4[lane * 8 + (wid ^ (lane & 7))];
        float4 xq1 = xs4[(lane + 32) * 8 + (wid ^ (lane & 7))];
        float xe0[4] = {xq0.x, xq0.y, xq0.z, xq0.w};
        float xe1[4] = {xq1.x, xq1.y, xq1.z, xq1.w};
#pragma unroll
        for (int e = 0; e < 4; e++) {
            const int il = wid * 4 + e;            // i within tile
            ulonglong2 b01 = bs2[il * 4 + 0];      // broadcast: r0..3
            ulonglong2 b23 = bs2[il * 4 + 1];      // r4..7
            ulonglong2 b45 = bs2[il * 4 + 2];      // r8..11
            ulonglong2 b67 = bs2[il * 4 + 3];      // r12..15
            u64 xx0 = pack2(xe0[e], xe0[e]);
            u64 xx1 = pack2(xe1[e], xe1[e]);
            ffma2(acc[0][0], xx0, b01.x);
            ffma2(acc[0][1], xx0, b01.y);
            ffma2(acc[0][2], xx0, b23.x);
            ffma2(acc[0][3], xx0, b23.y);
            ffma2(acc[0][4], xx0, b45.x);
            ffma2(acc[0][5], xx0, b45.y);
            ffma2(acc[0][6], xx0, b67.x);
            ffma2(acc[0][7], xx0, b67.y);
            ffma2(acc[1][0], xx1, b01.x);
            ffma2(acc[1][1], xx1, b01.y);
            ffma2(acc[1][2], xx1, b23.x);
            ffma2(acc[1][3], xx1, b23.y);
            ffma2(acc[1][4], xx1, b45.x);
            ffma2(acc[1][5], xx1, b45.y);
            ffma2(acc[1][6], xx1, b67.x);
            ffma2(acc[1][7], xx1, b67.y);
        }
    }
    __syncthreads();   // all compute done before reusing xs for reduction

    // cross-warp reduction through smem (reuse xs: 256 thr * 16 u64 = 32 KB)
    u64* red = reinterpret_cast<u64*>(&xs[0][0][0]);
#pragma unroll
    for (int s = 0; s < 2; s++)
#pragma unroll
        for (int j = 0; j < 8; j++)
            red[(wid * 32 + lane) * 16 + s * 8 + j] = acc[s][j];
    __syncthreads();

#pragma unroll
    for (int k = 0; k < 2; k++) {
        const int item = tid + k * 256;    // 0..511 -> (row, slot)
        const int row  = item >> 3;        // 0..63
        const int slot = item & 7;
        const int lrow = row & 31;
        const int rsel = row >> 5;
        u64 s = red[(0 * 32 + lrow) * 16 + rsel * 8 + slot];
#pragma unroll
        for (int w = 1; w < 8; w++)
            addf2(s, s, red[(w * 32 + lrow) * 16 + rsel * 8 + slot]);
        u64 two = pack2(2.0f, 2.0f);       // LoRA scale folded here
        mulf2(s, s, two);
        g_xbp[split][row0 + row][slot] = s;
    }
}

// ---------- kernel B: out = xb @ A (R4 design + row_base) ----------
// 128 threads; block covers 64 rows x 512 cols. A slice (16 r x 1 ulonglong2)
// in regs; xb (sum of 2 splits) broadcast from smem via LDS.128.
#define O_ROWS 64

__global__ void __launch_bounds__(128, 4) lora_out(const float* __restrict__ A,
                                                   float* __restrict__ out,
                                                   int row_base) {
    __shared__ u64 xbs[O_ROWS * R_DIM];   // 8 KB, entries packed (v,v)

    const int tid    = threadIdx.x;
    const int rowblk = blockIdx.x >> 3;
    const int colblk = blockIdx.x & 7;
    const int row0   = row_base + rowblk * O_ROWS;

    // fill xbs: 64 rows * 8 u64-slots = 512 -> 4 per thread; sum the 2 splits
    {
        const u64* g0 = &g_xbp[0][row0][0];
        const u64* g1 = &g_xbp[1][row0][0];
#pragma unroll
        for (int k = 0; k < 4; k++) {
            int j = tid + k * 128;            // j -> (row = j>>3, slot = j&7)
            u64 p;
            addf2(p, g0[j], g1[j]);
            float f0, f1;
            unpack2(p, f0, f1);
            int rw = j >> 3, slot = j & 7;
            xbs[rw * R_DIM + slot * 2 + 0] = pack2(f0, f0);
            xbs[rw * R_DIM + slot * 2 + 1] = pack2(f1, f1);
        }
    }
    __syncthreads();

    // A slice into registers: 16 r x 1 ulonglong2 (4 cols), coalesced
    const ulonglong2* Av = reinterpret_cast<const ulonglong2*>(A);  // [16][1024]
    const int cu = colblk * 128 + tid;    // ulonglong2 index within a row
    ulonglong2 Ar[R_DIM];
#pragma unroll
    for (int rr = 0; rr < R_DIM; rr++)
        Ar[rr] = Av[(size_t)rr * (OUT_DIM / 4) + cu];

    ulonglong2* outv = reinterpret_cast<ulonglong2*>(out);
    const ulonglong2* xu = reinterpret_cast<const ulonglong2*>(xbs);

#pragma unroll 2
    for (int rw = 0; rw < O_ROWS; rw++) {
        u64 a0e = 0ull, a0o = 0ull, a1e = 0ull, a1o = 0ull;
#pragma unroll
        for (int q = 0; q < 8; q++) {
            ulonglong2 xq = xu[rw * 8 + q];   // bcast (xb_2q,xb_2q),(xb_2q+1,..)
            ffma2(a0e, xq.x, Ar[2 * q].x);
            ffma2(a1e, xq.x, Ar[2 * q].y);
            ffma2(a0o, xq.y, Ar[2 * q + 1].x);
            ffma2(a1o, xq.y, Ar[2 * q + 1].y);
        }
        u64 o0, o1;
        addf2(o0, a0e, a0o);
        addf2(o1, a1e, a1o);
        ulonglong2 v; v.x = o0; v.y = o1;
        outv[(size_t)(row0 + rw) * (OUT_DIM / 4) + cu] = v;   // STG.128 coalesced
    }
}

// ---------- launch ----------
// 4 launches per call (2 xb halves + 2 out halves). Period-4 pattern puts
// ncu's captured launch (#6 with -s 5) on lora_xb.
extern "C" void kernel_launch(void* const* d_in, const int* in_sizes, int n_in,
                              void* d_out, int out_size) {
    const float* x  = (const float*)d_in[0];   // [4, 2048, 4096]
    const float* lA = (const float*)d_in[1];   // [16, 4096]
    const float* lB = (const float*)d_in[2];   // [4096, 16]
    float* out = (float*)d_out;

    const int HALF = ROWS_TOTAL / 2;
    const int xb_blocks  = (HALF / XB_ROWS) * XB_SPLIT;          // 128
    const int out_blocks = (HALF / O_ROWS) * (OUT_DIM / 512);    // 512

    lora_xb<<<xb_blocks, 256>>>(x, lB, 0);
    lora_xb<<<xb_blocks, 256>>>(x, lB, HALF);
    lora_out<<<out_blocks, 128>>>(lA, out, 0);
    lora_out<<<out_blocks, 128>>>(lA, out, HALF);
}

// round 11
// speedup vs baseline: 2.1763x; 1.3478x over previous
#include <cuda_runtime.h>
#include <cstdint>

// LoRA forward: out = (x @ B) @ A * 2
//   x: [8192, 4096] fp32, B: [4096, 16], A: [16, 4096], out: [8192, 4096]
//  lora_xb : R7 design (best measured ~35us): 64 rows/block, 2 rows/lane,
//            i-split x2, 4-stage cp.async pipeline (AT=32), 1 barrier/tile.
//            SINGLE launch, 256 blocks.
//  lora_out: R4 design (best measured ~29us): A slice in regs, xb broadcast
//            from smem, f32x2, 512-col blocks. SINGLE launch, 1024 blocks.

#define ROWS_TOTAL 8192
#define IN_DIM     4096
#define OUT_DIM    4096
#define R_DIM      16

#define XB_SPLIT   2
#define XB_ISPAN   (IN_DIM / XB_SPLIT)     // 2048 i per block
#define XB_AT      32                       // i per tile
#define XB_NT      (XB_ISPAN / XB_AT)       // 64 tiles
#define XB_ROWS    64                       // rows per block (2 per lane)
#define XB_STAGES  4

typedef unsigned long long u64;

// partial xb: [split][row][8] u64, each u64 = (xb_{2j}, xb_{2j+1}), scaled by 2
__device__ u64 g_xbp[XB_SPLIT][ROWS_TOTAL][R_DIM / 2];

// ---------- packed f32x2 helpers ----------
__device__ __forceinline__ u64 pack2(float lo, float hi) {
    u64 r; asm("mov.b64 %0, {%1, %2};" : "=l"(r) : "f"(lo), "f"(hi)); return r;
}
__device__ __forceinline__ void unpack2(u64 v, float& lo, float& hi) {
    asm("mov.b64 {%0, %1}, %2;" : "=f"(lo), "=f"(hi) : "l"(v));
}
__device__ __forceinline__ void ffma2(u64& d, u64 a, u64 b) {
    asm("fma.rn.f32x2 %0, %1, %2, %0;" : "+l"(d) : "l"(a), "l"(b));
}
__device__ __forceinline__ void addf2(u64& d, u64 a, u64 b) {
    asm("add.rn.f32x2 %0, %1, %2;" : "=l"(d) : "l"(a), "l"(b));
}
__device__ __forceinline__ void mulf2(u64& d, u64 a, u64 b) {
    asm("mul.rn.f32x2 %0, %1, %2;" : "=l"(d) : "l"(a), "l"(b));
}

// ---------- cp.async helpers ----------
__device__ __forceinline__ uint32_t s2u(const void* p) {
    return (uint32_t)__cvta_generic_to_shared(p);
}
__device__ __forceinline__ void cp16(uint32_t dst, const void* src) {
    asm volatile("cp.async.cg.shared.global [%0], [%1], 16;"
                 :: "r"(dst), "l"(src) : "memory");
}
#define CP_COMMIT()  asm volatile("cp.async.commit_group;" ::: "memory")
#define CP_WAIT(N)   asm volatile("cp.async.wait_group %0;" :: "n"(N) : "memory")

// ---------- kernel A: partial xb (R7 design) ----------
// 256 threads = 8 warps; lane covers rows {lane, lane+32}. Warp w covers
// i-subrange [w*4, w*4+4) of each 32-i tile. B consumed in NATIVE layout via
// broadcast LDS.128; x staged XOR-swizzled. 4-stage cp.async pipeline
// (prefetch depth 3), one barrier per tile.
__global__ void __launch_bounds__(256, 3) lora_xb(const float* __restrict__ x,
                                                  const float* __restrict__ B) {
    __shared__ float xs[XB_STAGES][XB_ROWS][XB_AT];   // 4 x 8 KB
    __shared__ float bs[XB_STAGES][XB_AT][R_DIM];     // 4 x 2 KB

    const int tid   = threadIdx.x;
    const int wid   = tid >> 5;
    const int lane  = tid & 31;
    const int row0  = (blockIdx.x >> 1) * XB_ROWS;
    const int i0    = (blockIdx.x & 1) * XB_ISPAN;
    const int split = blockIdx.x & 1;

    const float4* xg = reinterpret_cast<const float4*>(x);
    const float4* Bg = reinterpret_cast<const float4*>(B);   // B row i = 4 float4

    auto stage = [&](int it, int buf) {
        float4* xs4 = reinterpret_cast<float4*>(&xs[buf][0][0]);   // [64][8]
        float4* bs4 = reinterpret_cast<float4*>(&bs[buf][0][0]);   // [128]
        // x: 64 rows x 8 float4 = 512 -> 2 per thread, XOR-swizzled dst
#pragma unroll
        for (int k = 0; k < 2; k++) {
            int f  = tid + k * 256;
            int rw = f >> 3;          // 0..63
            int c4 = f & 7;           // 0..7
            cp16(s2u(&xs4[rw * 8 + (c4 ^ (rw & 7))]),
                 &xg[(size_t)(row0 + rw) * (IN_DIM / 4) + (i0 >> 2) + it * (XB_AT / 4) + c4]);
        }
        // B tile: 32 rows x 4 float4 = 128 contiguous -> threads 0..127
        if (tid < 128)
            cp16(s2u(&bs4[tid]), &Bg[(size_t)(i0 + it * XB_AT) * 4 + tid]);
        CP_COMMIT();
    };

    stage(0, 0);
    stage(1, 1);
    stage(2, 2);

    u64 acc[2][8];
#pragma unroll
    for (int s = 0; s < 2; s++)
#pragma unroll
        for (int j = 0; j < 8; j++) acc[s][j] = 0ull;

    for (int it = 0; it < XB_NT; it++) {
        const int buf = it % XB_STAGES;
        // complete tile `it`; keep the prefetched ones pending
        if      (it <= XB_NT - 3) { CP_WAIT(2); }
        else if (it == XB_NT - 2) { CP_WAIT(1); }
        else                      { CP_WAIT(0); }
        __syncthreads();   // tile `it` visible; compute of it-1 done everywhere,
                           // so buf (it+3)%4 (= buf of it-1) is free to restage
        if (it + 3 < XB_NT) stage(it + 3, (it + 3) % XB_STAGES);

        const float4*     xs4 = reinterpret_cast<const float4*>(&xs[buf][0][0]);
        const ulonglong2* bs2 = reinterpret_cast<const ulonglong2*>(&bs[buf][0][0]);

        // warp's i-slice: [wid*4, wid*4+4) = one float4 per row
        float4 xq0 = xs4[lane * 8 + (wid ^ (lane & 7))];
        float4 xq1 = xs4[(lane + 32) * 8 + (wid ^ (lane & 7))];
        float xe0[4] = {xq0.x, xq0.y, xq0.z, xq0.w};
        float xe1[4] = {xq1.x, xq1.y, xq1.z, xq1.w};
#pragma unroll
        for (int e = 0; e < 4; e++) {
            const int il = wid * 4 + e;            // i within tile
            ulonglong2 b01 = bs2[il * 4 + 0];      // broadcast: r0..3
            ulonglong2 b23 = bs2[il * 4 + 1];      // r4..7
            ulonglong2 b45 = bs2[il * 4 + 2];      // r8..11
            ulonglong2 b67 = bs2[il * 4 + 3];      // r12..15
            u64 xx0 = pack2(xe0[e], xe0[e]);
            u64 xx1 = pack2(xe1[e], xe1[e]);
            ffma2(acc[0][0], xx0, b01.x);
            ffma2(acc[0][1], xx0, b01.y);
            ffma2(acc[0][2], xx0, b23.x);
            ffma2(acc[0][3], xx0, b23.y);
            ffma2(acc[0][4], xx0, b45.x);
            ffma2(acc[0][5], xx0, b45.y);
            ffma2(acc[0][6], xx0, b67.x);
            ffma2(acc[0][7], xx0, b67.y);
            ffma2(acc[1][0], xx1, b01.x);
            ffma2(acc[1][1], xx1, b01.y);
            ffma2(acc[1][2], xx1, b23.x);
            ffma2(acc[1][3], xx1, b23.y);
            ffma2(acc[1][4], xx1, b45.x);
            ffma2(acc[1][5], xx1, b45.y);
            ffma2(acc[1][6], xx1, b67.x);
            ffma2(acc[1][7], xx1, b67.y);
        }
    }
    __syncthreads();   // all compute done before reusing xs for reduction

    // cross-warp reduction through smem (reuse xs: 256 thr * 16 u64 = 32 KB)
    u64* red = reinterpret_cast<u64*>(&xs[0][0][0]);
#pragma unroll
    for (int s = 0; s < 2; s++)
#pragma unroll
        for (int j = 0; j < 8; j++)
            red[(wid * 32 + lane) * 16 + s * 8 + j] = acc[s][j];
    __syncthreads();

#pragma unroll
    for (int k = 0; k < 2; k++) {
        const int item = tid + k * 256;    // 0..511 -> (row, slot)
        const int row  = item >> 3;        // 0..63
        const int slot = item & 7;
        const int lrow = row & 31;
        const int rsel = row >> 5;
        u64 s = red[(0 * 32 + lrow) * 16 + rsel * 8 + slot];
#pragma unroll
        for (int w = 1; w < 8; w++)
            addf2(s, s, red[(w * 32 + lrow) * 16 + rsel * 8 + slot]);
        u64 two = pack2(2.0f, 2.0f);       // LoRA scale folded here
        mulf2(s, s, two);
        g_xbp[split][row0 + row][slot] = s;
    }
}

// ---------- kernel B: out = xb @ A (R4 design) ----------
// 128 threads; block covers 64 rows x 512 cols. A slice (16 r x 1 ulonglong2)
// in regs; xb (sum of 2 splits) broadcast from smem via LDS.128. Grid 1024.
#define O_ROWS 64

__global__ void __launch_bounds__(128, 4) lora_out(const float* __restrict__ A,
                                                   float* __restrict__ out) {
    __shared__ u64 xbs[O_ROWS * R_DIM];   // 8 KB, entries packed (v,v)

    const int tid    = threadIdx.x;
    const int rowblk = blockIdx.x >> 3;
    const int colblk = blockIdx.x & 7;
    const int row0   = rowblk * O_ROWS;

    // fill xbs: 64 rows * 8 u64-slots = 512 -> 4 per thread; sum the 2 splits
    {
        const u64* g0 = &g_xbp[0][row0][0];
        const u64* g1 = &g_xbp[1][row0][0];
#pragma unroll
        for (int k = 0; k < 4; k++) {
            int j = tid + k * 128;            // j -> (row = j>>3, slot = j&7)
            u64 p;
            addf2(p, g0[j], g1[j]);
            float f0, f1;
            unpack2(p, f0, f1);
            int rw = j >> 3, slot = j & 7;
            xbs[rw * R_DIM + slot * 2 + 0] = pack2(f0, f0);
            xbs[rw * R_DIM + slot * 2 + 1] = pack2(f1, f1);
        }
    }
    __syncthreads();

    // A slice into registers: 16 r x 1 ulonglong2 (4 cols), coalesced
    const ulonglong2* Av = reinterpret_cast<const ulonglong2*>(A);  // [16][1024]
    const int cu = colblk * 128 + tid;    // ulonglong2 index within a row
    ulonglong2 Ar[R_DIM];
#pragma unroll
    for (int rr = 0; rr < R_DIM; rr++)
        Ar[rr] = Av[(size_t)rr * (OUT_DIM / 4) + cu];

    ulonglong2* outv = reinterpret_cast<ulonglong2*>(out);
    const ulonglong2* xu = reinterpret_cast<const ulonglong2*>(xbs);

#pragma unroll 2
    for (int rw = 0; rw < O_ROWS; rw++) {
        u64 a0e = 0ull, a0o = 0ull, a1e = 0ull, a1o = 0ull;
#pragma unroll
        for (int q = 0; q < 8; q++) {
            ulonglong2 xq = xu[rw * 8 + q];   // bcast (xb_2q,xb_2q),(xb_2q+1,..)
            ffma2(a0e, xq.x, Ar[2 * q].x);
            ffma2(a1e, xq.x, Ar[2 * q].y);
            ffma2(a0o, xq.y, Ar[2 * q + 1].x);
            ffma2(a1o, xq.y, Ar[2 * q + 1].y);
        }
        u64 o0, o1;
        addf2(o0, a0e, a0o);
        addf2(o1, a1e, a1o);
        ulonglong2 v; v.x = o0; v.y = o1;
        outv[(size_t)(row0 + rw) * (OUT_DIM / 4) + cu] = v;   // STG.128 coalesced
    }
}

// ---------- launch ----------
extern "C" void kernel_launch(void* const* d_in, const int* in_sizes, int n_in,
                              void* d_out, int out_size) {
    const float* x  = (const float*)d_in[0];   // [4, 2048, 4096]
    const float* lA = (const float*)d_in[1];   // [16, 4096]
    const float* lB = (const float*)d_in[2];   // [4096, 16]
    float* out = (float*)d_out;

    lora_xb<<<(ROWS_TOTAL / XB_ROWS) * XB_SPLIT, 256>>>(x, lB);          // 256
    lora_out<<<(ROWS_TOTAL / O_ROWS) * (OUT_DIM / 512), 128>>>(lA, out); // 1024
}